// round 2
// baseline (speedup 1.0000x reference)
#include <cuda_runtime.h>
#include <cuda_fp16.h>
#include <math.h>

#define BATCH 64
#define ONUM  32
#define INUM  512
#define DD    64
#define OD    (ONUM * DD)        // 2048
#define IB    16                 // i's per GEMM CTA

// ---------------- scratch (device globals; no allocation allowed) ------------
__device__ __half g_xhat[(size_t)BATCH * INUM * ONUM * DD]; // [b][i][o][d] 134MB fp16
__device__ float g_s[3][BATCH * OD];                        // s0, s1, s2
__device__ float g_out0[BATCH * OD];
__device__ float g_out1[BATCH * OD];
__device__ float g_b1[(size_t)BATCH * INUM * ONUM];         // [b][i][o]

// ---------------- packed f32x2 FMA (SASS FFMA2; ptxas won't emit from C++) ---
__device__ __forceinline__ void fma2(unsigned long long& d,
                                     unsigned long long a,
                                     unsigned long long b) {
    asm("fma.rn.f32x2 %0, %1, %2, %0;" : "+l"(d) : "l"(a), "l"(b));
}
__device__ __forceinline__ float ull_sum(unsigned long long v) {
    float lo = __uint_as_float((unsigned)(v & 0xffffffffULL));
    float hi = __uint_as_float((unsigned)(v >> 32));
    return lo + hi;
}

// ---------------- zero the atomic accumulators -------------------------------
__global__ void zero_s_kernel() {
    int idx = blockIdx.x * blockDim.x + threadIdx.x;
    if (idx < 3 * BATCH * OD) (&g_s[0][0])[idx] = 0.0f;
}

// ---------------- x_hat GEMM + fused s0 accumulation -------------------------
// grid (INUM/IB, ONUM), block 256.
// C[b][d] = sum_m x[b][i][m] * W[o][i][d][m], per (o,i). 64x64x64.
// K-pairs packed into f32x2 lanes: lo accumulates even m, hi odd m.
__global__ __launch_bounds__(256) void gemm_xhat_kernel(
    const float* __restrict__ x, const float* __restrict__ w)
{
    __shared__ float xs[64 * 68];  // [b][m], padded stride 68 (row start 16B-aligned)
    __shared__ float ws[64 * 68];  // [d][m]

    const int tid = threadIdx.x;
    const int o  = blockIdx.y;
    const int i0 = blockIdx.x * IB;
    const int ty = tid >> 4;        // 0..15 -> b block
    const int tx = tid & 15;        // 0..15 -> d block
    const int rb = ty * 4;
    const int cd = tx * 4;

    float s0acc[16];
#pragma unroll
    for (int k = 0; k < 16; k++) s0acc[k] = 0.0f;

    for (int ii = 0; ii < IB; ii++) {
        const int i = i0 + ii;
        // cooperative straight copies (m-contiguous, no transpose)
#pragma unroll
        for (int r = 0; r < 4; r++) {
            int idx = tid + r * 256;        // 0..1023
            int row = idx >> 4;             // b (or d)
            int f4  = idx & 15;             // which float4 along m
            *(float4*)&xs[row * 68 + f4 * 4] =
                *(const float4*)(x + ((size_t)row * INUM + i) * 64 + f4 * 4);
            *(float4*)&ws[row * 68 + f4 * 4] =
                *(const float4*)(w + (((size_t)o * INUM + i) * 64 + row) * 64 + f4 * 4);
        }
        __syncthreads();

        unsigned long long acc2[16];
#pragma unroll
        for (int k = 0; k < 16; k++) acc2[k] = 0ULL;

#pragma unroll
        for (int mc = 0; mc < 64; mc += 4) {
            ulonglong2 a2[4], b2[4];
#pragma unroll
            for (int j = 0; j < 4; j++)
                a2[j] = *(const ulonglong2*)&xs[(rb + j) * 68 + mc];
#pragma unroll
            for (int k = 0; k < 4; k++)
                b2[k] = *(const ulonglong2*)&ws[(cd + k) * 68 + mc];
#pragma unroll
            for (int j = 0; j < 4; j++)
#pragma unroll
                for (int k = 0; k < 4; k++) {
                    fma2(acc2[j * 4 + k], a2[j].x, b2[k].x);
                    fma2(acc2[j * 4 + k], a2[j].y, b2[k].y);
                }
        }

        // reduce lo+hi, store x_hat fp16, accumulate s0
#pragma unroll
        for (int jb = 0; jb < 4; jb++) {
            float f0 = ull_sum(acc2[jb * 4 + 0]);
            float f1 = ull_sum(acc2[jb * 4 + 1]);
            float f2 = ull_sum(acc2[jb * 4 + 2]);
            float f3 = ull_sum(acc2[jb * 4 + 3]);
            __half* p = g_xhat + ((size_t)(rb + jb) * INUM + i) * (size_t)OD + o * DD + cd;
            *(half2*)p       = __floats2half2_rn(f0, f1);
            *(half2*)(p + 2) = __floats2half2_rn(f2, f3);
            s0acc[jb * 4 + 0] += f0;
            s0acc[jb * 4 + 1] += f1;
            s0acc[jb * 4 + 2] += f2;
            s0acc[jb * 4 + 3] += f3;
        }
        __syncthreads();
    }

    const float sc = 1.0f / (float)ONUM;   // softmax of zeros
#pragma unroll
    for (int jb = 0; jb < 4; jb++)
#pragma unroll
        for (int jd = 0; jd < 4; jd++)
            atomicAdd(&g_s[0][(rb + jb) * OD + o * DD + cd + jd],
                      s0acc[jb * 4 + jd] * sc);
}

// ---------------- squash: v = (n2/(1+n2)) * s / (n + 1e-8) -------------------
// one warp per (b,o) row of 64
__global__ void squash_kernel(const float* __restrict__ s, float* __restrict__ v)
{
    int gw   = (blockIdx.x * blockDim.x + threadIdx.x) >> 5;
    int lane = threadIdx.x & 31;
    if (gw >= BATCH * ONUM) return;
    const float* row = s + (size_t)gw * 64;
    float a = row[lane];
    float b = row[lane + 32];
    float ss = a * a + b * b;
#pragma unroll
    for (int off = 16; off; off >>= 1) ss += __shfl_xor_sync(0xffffffffu, ss, off);
    float n = sqrtf(ss);
    float f = (ss / (1.0f + ss)) / (n + 1e-8f);
    v[(size_t)gw * 64 + lane]      = a * f;
    v[(size_t)gw * 64 + lane + 32] = b * f;
}

// ---------------- fused routing pass -----------------------------------------
// MODE 0: logits = agree(out_prev); write b1; accumulate s_next
// MODE 1: logits = b1 + agree(out_prev); accumulate s_next
// grid (BATCH, INUM/32), block 256. Each CTA: one b, 32 i's, all o.
// Thread's 8-element slice (o=tid>>3, d=(tid&7)*8..+7) == x_hat + tid*8:
// ONE LDG.128 per thread per i serves both agreement dot and accumulate.
template <int MODE>
__global__ __launch_bounds__(256) void route_pass_kernel(
    const float* __restrict__ out_prev, float* __restrict__ s_next)
{
    __shared__ float tarr[ONUM];
    __shared__ float carr[ONUM];

    const int tid = threadIdx.x;
    const int b   = blockIdx.x;
    const int i0  = blockIdx.y * 32;
    const int og  = tid >> 3;      // o index
    const int l8  = tid & 7;

    // out_prev slice in registers
    float opv[8];
    const float* oprow = out_prev + (size_t)b * OD + tid * 8;
#pragma unroll
    for (int j = 0; j < 8; j++) opv[j] = oprow[j];

    float sacc[8];
#pragma unroll
    for (int j = 0; j < 8; j++) sacc[j] = 0.0f;

    const __half* bp = g_xhat + ((size_t)b * INUM + i0) * (size_t)OD + tid * 8;
    float* b1p = g_b1 + ((size_t)b * INUM + i0) * ONUM + og;

    // register prefetch depth 2
    uint4 n0 = *(const uint4*)bp;
    uint4 n1 = *(const uint4*)(bp + OD);

    for (int ii = 0; ii < 32; ii++) {
        uint4 cur = n0;
        n0 = n1;
        if (ii + 2 < 32) n1 = *(const uint4*)(bp + (size_t)(ii + 2) * OD);

        const __half2* hp = (const __half2*)&cur;
        float2 f0 = __half22float2(hp[0]);
        float2 f1 = __half22float2(hp[1]);
        float2 f2 = __half22float2(hp[2]);
        float2 f3 = __half22float2(hp[3]);

        // agreement dot partial (8 lanes per o)
        float p = f0.x * opv[0] + f0.y * opv[1] + f1.x * opv[2] + f1.y * opv[3]
                + f2.x * opv[4] + f2.y * opv[5] + f3.x * opv[6] + f3.y * opv[7];
        p += __shfl_down_sync(0xffffffffu, p, 4, 8);
        p += __shfl_down_sync(0xffffffffu, p, 2, 8);
        p += __shfl_down_sync(0xffffffffu, p, 1, 8);
        if (l8 == 0) {
            if (MODE == 1) p += b1p[ii * ONUM];
            else           b1p[ii * ONUM] = p;
            tarr[og] = p;
        }
        __syncthreads();

        // softmax over the 32 o's (warp 0)
        if (tid < 32) {
            float t = tarr[tid];
            float m = t;
#pragma unroll
            for (int off = 16; off; off >>= 1)
                m = fmaxf(m, __shfl_xor_sync(0xffffffffu, m, off));
            float e = expf(t - m);
            float s = e;
#pragma unroll
            for (int off = 16; off; off >>= 1)
                s += __shfl_xor_sync(0xffffffffu, s, off);
            carr[tid] = e / s;
        }
        __syncthreads();

        // weighted accumulate (reuses the registers already loaded)
        float c = carr[og];
        sacc[0] += c * f0.x; sacc[1] += c * f0.y;
        sacc[2] += c * f1.x; sacc[3] += c * f1.y;
        sacc[4] += c * f2.x; sacc[5] += c * f2.y;
        sacc[6] += c * f3.x; sacc[7] += c * f3.y;
    }

    float* sp = s_next + (size_t)b * OD + tid * 8;
#pragma unroll
    for (int j = 0; j < 8; j++) atomicAdd(sp + j, sacc[j]);
}

// ---------------- launch ------------------------------------------------------
extern "C" void kernel_launch(void* const* d_in, const int* in_sizes, int n_in,
                              void* d_out, int out_size)
{
    const float* x = (const float*)d_in[0];
    const float* w = (const float*)d_in[1];
    float* out = (float*)d_out;

    float* s_base;  cudaGetSymbolAddress((void**)&s_base,  g_s);
    float* out0;    cudaGetSymbolAddress((void**)&out0,    g_out0);
    float* out1;    cudaGetSymbolAddress((void**)&out1,    g_out1);
    float* s0 = s_base;
    float* s1 = s_base + BATCH * OD;
    float* s2 = s_base + 2 * BATCH * OD;

    zero_s_kernel<<<(3 * BATCH * OD + 255) / 256, 256>>>();

    gemm_xhat_kernel<<<dim3(INUM / IB, ONUM), 256>>>(x, w);

    squash_kernel<<<(BATCH * ONUM) / 8, 256>>>(s0, out0);

    route_pass_kernel<0><<<dim3(BATCH, INUM / 32), 256>>>(out0, s1);

    squash_kernel<<<(BATCH * ONUM) / 8, 256>>>(s1, out1);

    route_pass_kernel<1><<<dim3(BATCH, INUM / 32), 256>>>(out1, s2);

    squash_kernel<<<(BATCH * ONUM) / 8, 256>>>(s2, out);
}

// round 4
// speedup vs baseline: 3.9595x; 3.9595x over previous
#include <cuda_runtime.h>
#include <cuda_fp16.h>
#include <cstdint>
#include <math.h>

#define BATCH 64
#define ONUM  32
#define INUM  512
#define DD    64
#define OD    2048               // ONUM*DD

// ---------------- scratch (device globals) -----------------------------------
__device__ __half g_xhat[(size_t)BATCH * INUM * OD];   // [b][i][o][d] fp16, 134MB
__device__ float g_s[3][BATCH * OD];
__device__ float g_out0[BATCH * OD];
__device__ float g_out1[BATCH * OD];
__device__ float g_b1[(size_t)BATCH * INUM * ONUM];

// ---------------- helpers -----------------------------------------------------
__device__ __forceinline__ uint32_t smem_u32(const void* p) {
    uint32_t a;
    asm("{ .reg .u64 t; cvta.to.shared.u64 t, %1; cvt.u32.u64 %0, t; }" : "=r"(a) : "l"(p));
    return a;
}
__device__ __forceinline__ uint2 f4_to_h4(float4 v) {
    __half2 h0 = __floats2half2_rn(v.x, v.y);
    __half2 h1 = __floats2half2_rn(v.z, v.w);
    return make_uint2(*(uint32_t*)&h0, *(uint32_t*)&h1);
}
__device__ __forceinline__ uint32_t f2_to_h2(float a, float b) {
    __half2 h = __floats2half2_rn(a, b);
    return *(uint32_t*)&h;
}
__device__ __forceinline__ void ldmx4(uint32_t* r, uint32_t addr) {
    asm volatile("ldmatrix.sync.aligned.m8n8.x4.shared.b16 {%0,%1,%2,%3}, [%4];"
                 : "=r"(r[0]), "=r"(r[1]), "=r"(r[2]), "=r"(r[3]) : "r"(addr));
}
__device__ __forceinline__ void mma16816(float* c, const uint32_t* a, uint32_t b0, uint32_t b1) {
    asm volatile("mma.sync.aligned.m16n8k16.row.col.f32.f16.f16.f32 "
                 "{%0,%1,%2,%3}, {%4,%5,%6,%7}, {%8,%9}, {%0,%1,%2,%3};"
                 : "+f"(c[0]), "+f"(c[1]), "+f"(c[2]), "+f"(c[3])
                 : "r"(a[0]), "r"(a[1]), "r"(a[2]), "r"(a[3]), "r"(b0), "r"(b1));
}

// ---------------- zero --------------------------------------------------------
__global__ void zero_s_kernel() {
    int idx = blockIdx.x * blockDim.x + threadIdx.x;
    if (idx < 3 * BATCH * OD) (&g_s[0][0])[idx] = 0.0f;
}

// ---------------- HMMA GEMM: x_hat + fused s0 ---------------------------------
// grid (16 o-pairs, 32 i-groups), block 256 (8 warps). Per i:
//   A = x[:,i,:] [b=64][m=64], B = W[2p..2p+1][i] [od=128][m=64] (col-major B).
//   D[b][od] via m16n8k16; warp (wm=wid&1, wn=wid>>1) owns 32b x 32od.
#define WT_S 72     // W tile row stride (halves)
#define XT_S 72
#define OT_S 136    // out stage row stride (halves), 272B = 16B-aligned rows

__global__ __launch_bounds__(256, 2) void gemm_xhat_hmma(
    const float* __restrict__ x, const float* __restrict__ w)
{
    __shared__ __align__(16) __half Wt[128 * WT_S];  // [od][m]
    __shared__ __align__(16) __half Xt[64 * XT_S];   // [b][m]
    __shared__ __align__(16) __half Ot[64 * OT_S];   // [b][od 0..127]

    const int tid = threadIdx.x, wid = tid >> 5, lane = tid & 31;
    const int p = blockIdx.x;                   // o-pair
    const int ibase = blockIdx.y * 16;

    const uint32_t wbase = smem_u32(Wt);
    const uint32_t xbase = smem_u32(Xt);

    const float4* wf4 = (const float4*)w;
    const float4* xf4 = (const float4*)x;

    const int wm = wid & 1;          // b-half (32 rows)
    const int wn = wid >> 1;         // od-quarter (32 cols)
    const int r0a = wm * 32;
    const int n0  = wn * 32;

    // precomputed ldmatrix lane addressing pieces
    const int a_row_off = (lane & 7) + ((lane >> 3) & 1) * 8;
    const int a_col_off = (lane >= 16) ? 8 : 0;
    const int b_row_off = (lane & 7) + ((lane >> 4) & 1) * 8;
    const int b_col_off = ((lane >> 3) & 1) * 8;

    float s0acc[4][8];
#pragma unroll
    for (int j = 0; j < 4; j++)
#pragma unroll
        for (int e = 0; e < 8; e++) s0acc[j][e] = 0.0f;

    for (int t = 0; t < 16; t++) {
        const int i = ibase + t;

        // ---- phase 1: load + convert + STS tiles ----
#pragma unroll
        for (int k = 0; k < 8; k++) {
            int g = tid + k * 256;              // 0..2047
            int ol = g >> 10, rem = g & 1023;   // d = rem>>4, mq = rem&15
            float4 v = wf4[(((size_t)(2 * p + ol) * INUM + i) << 10) + rem];
            *(uint2*)&Wt[(ol * 64 + (rem >> 4)) * WT_S + (rem & 15) * 4] = f4_to_h4(v);
        }
#pragma unroll
        for (int j = 0; j < 4; j++) {
            int idx = tid + j * 256;            // 0..1023
            int b = idx >> 4, mq = idx & 15;
            float4 v = xf4[((size_t)b * INUM + i) * 16 + mq];
            *(uint2*)&Xt[b * XT_S + mq * 4] = f4_to_h4(v);
        }
        __syncthreads();

        // ---- phase 2: mma ----
        float acc[2][4][4];
#pragma unroll
        for (int mt = 0; mt < 2; mt++)
#pragma unroll
            for (int nt = 0; nt < 4; nt++)
#pragma unroll
                for (int e = 0; e < 4; e++) acc[mt][nt][e] = 0.0f;

#pragma unroll
        for (int ks = 0; ks < 4; ks++) {
            const int kc = ks * 16;
            uint32_t afr[2][4], bfr[2][4];
#pragma unroll
            for (int mt = 0; mt < 2; mt++) {
                int row = r0a + mt * 16 + a_row_off;
                int col = kc + a_col_off;
                ldmx4(afr[mt], xbase + (row * XT_S + col) * 2);
            }
#pragma unroll
            for (int nt2 = 0; nt2 < 2; nt2++) {
                int row = n0 + nt2 * 16 + b_row_off;
                int col = kc + b_col_off;
                ldmx4(bfr[nt2], wbase + (row * WT_S + col) * 2);
            }
#pragma unroll
            for (int mt = 0; mt < 2; mt++) {
#pragma unroll
                for (int nt = 0; nt < 4; nt++) {
                    uint32_t b0 = bfr[nt >> 1][(nt & 1) * 2 + 0];
                    uint32_t b1 = bfr[nt >> 1][(nt & 1) * 2 + 1];
                    mma16816(acc[mt][nt], afr[mt], b0, b1);
                }
            }
        }

        // ---- phase 3: stage D into Ot (fp16) ----
#pragma unroll
        for (int mt = 0; mt < 2; mt++) {
            int row = r0a + mt * 16 + (lane >> 2);
#pragma unroll
            for (int nt = 0; nt < 4; nt++) {
                int col = n0 + nt * 8 + (lane & 3) * 2;
                *(uint32_t*)&Ot[row * OT_S + col] = f2_to_h2(acc[mt][nt][0], acc[mt][nt][1]);
                *(uint32_t*)&Ot[(row + 8) * OT_S + col] = f2_to_h2(acc[mt][nt][2], acc[mt][nt][3]);
            }
        }
        __syncthreads();

        // ---- phase 4: coalesced store + s0 accumulation ----
#pragma unroll
        for (int j = 0; j < 4; j++) {
            int idx = tid + j * 256;
            int brow = idx >> 4, chunk = idx & 15;
            uint4 v = *(const uint4*)&Ot[brow * OT_S + chunk * 8];
            const __half2* h = (const __half2*)&v;
#pragma unroll
            for (int q = 0; q < 4; q++) {
                float2 f = __half22float2(h[q]);
                s0acc[j][q * 2 + 0] += f.x;
                s0acc[j][q * 2 + 1] += f.y;
            }
            *(uint4*)&g_xhat[((size_t)brow * INUM + i) * OD + p * 128 + chunk * 8] = v;
        }
        __syncthreads();
    }

    // s0 atomics (once per CTA)
    const float sc = 1.0f / (float)ONUM;
#pragma unroll
    for (int j = 0; j < 4; j++) {
        int idx = tid + j * 256;
        int brow = idx >> 4, chunk = idx & 15;
        float* sp = &g_s[0][brow * OD + p * 128 + chunk * 8];
#pragma unroll
        for (int e = 0; e < 8; e++)
            atomicAdd(sp + e, s0acc[j][e] * sc);
    }
}

// ---------------- squash ------------------------------------------------------
__global__ void squash_kernel(const float* __restrict__ s, float* __restrict__ v)
{
    int gw   = (blockIdx.x * blockDim.x + threadIdx.x) >> 5;
    int lane = threadIdx.x & 31;
    if (gw >= BATCH * ONUM) return;
    const float* row = s + (size_t)gw * 64;
    float a = row[lane];
    float b = row[lane + 32];
    float ss = a * a + b * b;
#pragma unroll
    for (int off = 16; off; off >>= 1) ss += __shfl_xor_sync(0xffffffffu, ss, off);
    float n = sqrtf(ss);
    float f = (ss / (1.0f + ss)) / (n + 1e-8f);
    v[(size_t)gw * 64 + lane]      = a * f;
    v[(size_t)gw * 64 + lane + 32] = b * f;
}

// ---------------- warp-synchronous routing pass -------------------------------
// grid (64, 4), block 128 (4 warps). warp -> (b, slice of 32 i's); lane = o.
template <int MODE>
__global__ __launch_bounds__(128) void route_tc(
    const float* __restrict__ out_prev, float* __restrict__ s_next)
{
    __shared__ float red[ONUM * 65];

    const int tid = threadIdx.x, wid = tid >> 5, lane = tid & 31;
    const int b = blockIdx.x;
    const int i0 = (blockIdx.y * 4 + wid) * 32;

    for (int k = tid; k < ONUM * 65; k += 128) red[k] = 0.0f;

    float opv[64];
    {
        const float4* opf = (const float4*)(out_prev + (size_t)b * OD + lane * 64);
#pragma unroll
        for (int c = 0; c < 16; c++) {
            float4 v = opf[c];
            opv[c * 4 + 0] = v.x; opv[c * 4 + 1] = v.y;
            opv[c * 4 + 2] = v.z; opv[c * 4 + 3] = v.w;
        }
    }
    __syncthreads();

    float sacc[64];
#pragma unroll
    for (int d = 0; d < 64; d++) sacc[d] = 0.0f;

    const uint4* xp = (const uint4*)(g_xhat + (size_t)b * INUM * OD + (size_t)i0 * OD + lane * 64);
    float* b1p = g_b1 + ((size_t)b * INUM + i0) * ONUM + lane;

    uint4 cur[8], nxt[8];
#pragma unroll
    for (int c = 0; c < 8; c++) cur[c] = xp[c];

    for (int ii = 0; ii < 32; ii++) {
        if (ii + 1 < 32) {
            const uint4* np = xp + (size_t)(ii + 1) * (OD / 8);
#pragma unroll
            for (int c = 0; c < 8; c++) nxt[c] = np[c];
        }

        float pdot = 0.0f;
#pragma unroll
        for (int c = 0; c < 8; c++) {
            const __half2* h = (const __half2*)&cur[c];
            float2 f0 = __half22float2(h[0]);
            float2 f1 = __half22float2(h[1]);
            float2 f2 = __half22float2(h[2]);
            float2 f3 = __half22float2(h[3]);
            pdot += f0.x * opv[c * 8 + 0] + f0.y * opv[c * 8 + 1]
                  + f1.x * opv[c * 8 + 2] + f1.y * opv[c * 8 + 3]
                  + f2.x * opv[c * 8 + 4] + f2.y * opv[c * 8 + 5]
                  + f3.x * opv[c * 8 + 6] + f3.y * opv[c * 8 + 7];
        }
        if (MODE == 1) pdot += b1p[ii * ONUM];
        else           b1p[ii * ONUM] = pdot;

        float m = pdot;
#pragma unroll
        for (int off = 16; off; off >>= 1)
            m = fmaxf(m, __shfl_xor_sync(0xffffffffu, m, off));
        float e = __expf(pdot - m);
        float ssum = e;
#pragma unroll
        for (int off = 16; off; off >>= 1)
            ssum += __shfl_xor_sync(0xffffffffu, ssum, off);
        float c = e / ssum;

#pragma unroll
        for (int cc = 0; cc < 8; cc++) {
            const __half2* h = (const __half2*)&cur[cc];
            float2 f0 = __half22float2(h[0]);
            float2 f1 = __half22float2(h[1]);
            float2 f2 = __half22float2(h[2]);
            float2 f3 = __half22float2(h[3]);
            sacc[cc * 8 + 0] += c * f0.x; sacc[cc * 8 + 1] += c * f0.y;
            sacc[cc * 8 + 2] += c * f1.x; sacc[cc * 8 + 3] += c * f1.y;
            sacc[cc * 8 + 4] += c * f2.x; sacc[cc * 8 + 5] += c * f2.y;
            sacc[cc * 8 + 6] += c * f3.x; sacc[cc * 8 + 7] += c * f3.y;
        }
#pragma unroll
        for (int c2 = 0; c2 < 8; c2++) cur[c2] = nxt[c2];
    }

#pragma unroll
    for (int d = 0; d < 64; d++)
        atomicAdd(&red[lane * 65 + d], sacc[d]);
    __syncthreads();

    for (int k = tid; k < OD; k += 128) {
        int o = k >> 6, d = k & 63;
        atomicAdd(&s_next[(size_t)b * OD + k], red[o * 65 + d]);
    }
}

// ---------------- launch ------------------------------------------------------
extern "C" void kernel_launch(void* const* d_in, const int* in_sizes, int n_in,
                              void* d_out, int out_size)
{
    const float* x = (const float*)d_in[0];
    const float* w = (const float*)d_in[1];
    float* out = (float*)d_out;

    float* s_base;  cudaGetSymbolAddress((void**)&s_base,  g_s);
    float* out0;    cudaGetSymbolAddress((void**)&out0,    g_out0);
    float* out1;    cudaGetSymbolAddress((void**)&out1,    g_out1);
    float* s0 = s_base;
    float* s1 = s_base + BATCH * OD;
    float* s2 = s_base + 2 * BATCH * OD;

    zero_s_kernel<<<(3 * BATCH * OD + 255) / 256, 256>>>();

    gemm_xhat_hmma<<<dim3(16, 32), 256>>>(x, w);

    squash_kernel<<<(BATCH * ONUM) / 8, 256>>>(s0, out0);

    route_tc<0><<<dim3(BATCH, 4), 128>>>(out0, s1);

    squash_kernel<<<(BATCH * ONUM) / 8, 256>>>(s1, out1);

    route_tc<1><<<dim3(BATCH, 4), 128>>>(out1, s2);

    squash_kernel<<<(BATCH * ONUM) / 8, 256>>>(s2, out);
}